// round 13
// baseline (speedup 1.0000x reference)
#include <cuda_runtime.h>
#include <cuda_fp16.h>
#include <math.h>
#include <stdint.h>

#define BB 2
#define SS 1024
#define EE 512
#define HH 64
#define DKK 8
#define FF 2048
#define BS (BB*SS)   // 2048

// ---- scratch (device globals: allocation-free) ----
__device__ float g_q[BB*HH*SS*DKK];   // [B][H][S][8]
__device__ float g_attn[BS*EE];
__device__ float g_x1[BS*EE];
__device__ float g_qf[BS*EE];
__device__ float g_hdn[BS*FF];
__device__ float g_pre[BS*EE];

__device__ __forceinline__ float ex2a(float x) {
    float r; asm("ex2.approx.f32 %0, %1;" : "=f"(r) : "f"(x)); return r;
}
// m16n8k8 tf32 mma (attention scores)
__device__ __forceinline__ void mma_tf32u(float& c0, float& c1, float& c2, float& c3,
                                          uint32_t A0, uint32_t A1, uint32_t A2, uint32_t A3,
                                          uint32_t B0, uint32_t B1) {
    asm volatile(
        "mma.sync.aligned.m16n8k8.row.col.f32.tf32.tf32.f32 "
        "{%0,%1,%2,%3},{%4,%5,%6,%7},{%8,%9},{%0,%1,%2,%3};"
        : "+f"(c0), "+f"(c1), "+f"(c2), "+f"(c3)
        : "r"(A0), "r"(A1), "r"(A2), "r"(A3), "r"(B0), "r"(B1));
}
// m16n8k16 fp16 mma, f32 accumulate
__device__ __forceinline__ void mma_f16(float* acc,
                                        uint32_t a0, uint32_t a1, uint32_t a2, uint32_t a3,
                                        uint32_t b0, uint32_t b1) {
    asm volatile(
        "mma.sync.aligned.m16n8k16.row.col.f32.f16.f16.f32 "
        "{%0,%1,%2,%3},{%4,%5,%6,%7},{%8,%9},{%0,%1,%2,%3};"
        : "+f"(acc[0]), "+f"(acc[1]), "+f"(acc[2]), "+f"(acc[3])
        : "r"(a0), "r"(a1), "r"(a2), "r"(a3), "r"(b0), "r"(b1));
}
__device__ __forceinline__ uint32_t pack_h2(float lo, float hi) {
    __half2 h = __floats2half2_rn(lo, hi);
    return *reinterpret_cast<uint32_t*>(&h);
}

// =====================================================================
// K1: ring expvals
// =====================================================================
__global__ void qkv_kernel(const float* __restrict__ x,
                           const float* __restrict__ theta) {
    int i = blockIdx.x * 256 + threadIdx.x;
    int h  = i & (HH-1);
    int bs = i >> 6;
    const float* xp = x + bs*EE + h*DKK;
    float4 xa = *(const float4*)xp;
    float4 xb = *(const float4*)(xp + 4);
    float c0 = __cosf(xa.x + theta[0]);
    float c1 = __cosf(xa.y + theta[1]);
    float c2 = __cosf(xa.z + theta[2]);
    float c3 = __cosf(xa.w + theta[3]);
    float c4 = __cosf(xb.x + theta[4]);
    float c5 = __cosf(xb.y + theta[5]);
    float c6 = __cosf(xb.z + theta[6]);
    float c7 = __cosf(xb.w + theta[7]);
    float o1 = c0*c1;
    float o2 = o1*c2;
    float o3 = o2*c3;
    float o4 = o3*c4;
    float o5 = o4*c5;
    float o6 = o5*c6;
    float o7 = o6*c7;
    float o0 = c1*c2*c3*c4*c5*c6*c7;
    int b = bs >> 10, s = bs & (SS-1);
    float* qp = g_q + (((b*HH + h)*SS) + s)*DKK;
    *(float4*)qp       = make_float4(o0, o1, o2, o3);
    *(float4*)(qp + 4) = make_float4(o4, o5, o6, o7);
}

// =====================================================================
// K2: tensor-core attention (dynamic smem: 48KB Ks floats + 16KB Vh half2).
// Scores: 2x tf32 m16n8k8 per 16 tokens (unpermuted B rows).
// Unpermuted scores C-layout gives lane(g,tc) ADJACENT tokens {2tc,2tc+1}
// -> exp + pack_h2 lands directly in the fp16 m16n8k16 A-fragment.
// AV: ONE fp16 k16 MMA per 16 tokens. V token-pair-packed (8tc+g banks, CF).
// =====================================================================
#define ATTN_SMEM (SS*12*4 + (SS/2)*8*4)   // 49152 + 16384 = 65536

__global__ void __launch_bounds__(256) attn_mma_kernel() {
    extern __shared__ char smem_raw[];
    float*   Ks = reinterpret_cast<float*>(smem_raw);                 // [SS*12]
    __half2* Vh = reinterpret_cast<__half2*>(smem_raw + SS*12*4);     // [SS/2][8]

    const int bh   = blockIdx.x >> 3;
    const int tile = blockIdx.x & 7;

    const float* qsrc = g_q + bh*(SS*DKK);
    const float4* q4 = (const float4*)qsrc;          // q4[t*2 + hf]
    for (int j = threadIdx.x; j < SS*DKK/4; j += 256) {
        float4 v = q4[j];
        int t = j >> 1, hf = (j & 1) * 4;
        *(float4*)&Ks[t*12 + hf] = v;
    }
    for (int j = threadIdx.x; j < SS; j += 256) {    // j = (tp, hf)
        int tp = j >> 1, hf = j & 1;
        float4 va = q4[(2*tp  )*2 + hf];
        float4 vb = q4[(2*tp+1)*2 + hf];
        uint4 pk;
        pk.x = pack_h2(va.x, vb.x);
        pk.y = pack_h2(va.y, vb.y);
        pk.z = pack_h2(va.z, vb.z);
        pk.w = pack_h2(va.w, vb.w);
        *reinterpret_cast<uint4*>(&Vh[tp*8 + hf*4]) = pk;
    }
    __syncthreads();

    const int lane = threadIdx.x & 31, warp = threadIdx.x >> 5;
    const int g = lane >> 2, tc = lane & 3;
    const int row0 = tile*128 + warp*16;

    const float SCL = 0.35355339059f * 1.44269504089f;   // 1/sqrt(8)*log2(e)
    const uint32_t qa0 = __float_as_uint(Ks[(row0+g  )*12 + tc  ] * SCL);
    const uint32_t qa1 = __float_as_uint(Ks[(row0+g+8)*12 + tc  ] * SCL);
    const uint32_t qa2 = __float_as_uint(Ks[(row0+g  )*12 + tc+4] * SCL);
    const uint32_t qa3 = __float_as_uint(Ks[(row0+g+8)*12 + tc+4] * SCL);

    float o0=0.f, o1=0.f, o2=0.f, o3=0.f;   // single AV accumulator set
    float rs0=0.f, rs1=0.f;                 // rowsums (rows g, g+8)

    #pragma unroll 4
    for (int t0 = 0; t0 < SS; t0 += 16) {
        // scores B-frags, natural token rows (banks 12g+tc: bijective mod 32)
        uint32_t sA0 = __float_as_uint(Ks[(t0+g  )*12 + tc  ]);
        uint32_t sA1 = __float_as_uint(Ks[(t0+g  )*12 + tc+4]);
        uint32_t sB0 = __float_as_uint(Ks[(t0+8+g)*12 + tc  ]);
        uint32_t sB1 = __float_as_uint(Ks[(t0+8+g)*12 + tc+4]);
        float a0=0.f,a1=0.f,a2=0.f,a3=0.f;   // tokens t0..t0+7
        float b0=0.f,b1=0.f,b2=0.f,b3=0.f;   // tokens t0+8..t0+15
        mma_tf32u(a0,a1,a2,a3, qa0,qa1,qa2,qa3, sA0,sA1);
        mma_tf32u(b0,b1,b2,b3, qa0,qa1,qa2,qa3, sB0,sB1);

        // exp2 on MUFU; lane(g,tc) holds rows g/g+8 cols {2tc,2tc+1}
        float pA0 = ex2a(a0), pA1 = ex2a(a1), pA2 = ex2a(a2), pA3 = ex2a(a3);
        float pB0 = ex2a(b0), pB1 = ex2a(b1), pB2 = ex2a(b2), pB3 = ex2a(b3);
        rs0 += pA0 + pA1 + pB0 + pB1;
        rs1 += pA2 + pA3 + pB2 + pB3;

        // k16 A-frag: packed adjacent-token pairs, zero shuffles
        uint32_t fa0 = pack_h2(pA0, pA1);
        uint32_t fa1 = pack_h2(pA2, pA3);
        uint32_t fa2 = pack_h2(pB0, pB1);
        uint32_t fa3 = pack_h2(pB2, pB3);
        // k16 B-frag: Vh[t0/2 + tc][g], Vh[t0/2 + tc+4][g]
        uint32_t vb0 = *reinterpret_cast<const uint32_t*>(&Vh[((t0>>1)+tc  )*8 + g]);
        uint32_t vb1 = *reinterpret_cast<const uint32_t*>(&Vh[((t0>>1)+tc+4)*8 + g]);
        float acc[4] = {o0, o1, o2, o3};
        mma_f16(acc, fa0, fa1, fa2, fa3, vb0, vb1);
        o0 = acc[0]; o1 = acc[1]; o2 = acc[2]; o3 = acc[3];
    }

    rs0 += __shfl_xor_sync(0xffffffffu, rs0, 1);
    rs0 += __shfl_xor_sync(0xffffffffu, rs0, 2);
    rs1 += __shfl_xor_sync(0xffffffffu, rs1, 1);
    rs1 += __shfl_xor_sync(0xffffffffu, rs1, 2);
    float i0 = 1.0f / rs0, i1 = 1.0f / rs1;

    const int b = bh >> 6, h = bh & (HH-1);
    const int r0 = row0 + g, r1 = r0 + 8;
    float* d0 = g_attn + (b*SS + r0)*EE + h*DKK + 2*tc;
    float* d1 = g_attn + (b*SS + r1)*EE + h*DKK + 2*tc;
    *(float2*)d0 = make_float2(o0*i0, o1*i0);
    *(float2*)d1 = make_float2(o2*i1, o3*i1);
}

// =====================================================================
// fp16 m16n8k16 tensor-core GEMM (validated R10): out = A @ W (+bias,+res,relu)
// =====================================================================
template<int KTOT, bool RELU>
__global__ void __launch_bounds__(256) mma_gemm_kernel(
    const float* __restrict__ A, const float* __restrict__ W,
    const float* __restrict__ bias, const float* __restrict__ res,
    float* __restrict__ out, int N)
{
    __shared__ __half As[32][40];
    __shared__ __half2 Bs[16][136];

    const int rowbase = blockIdx.y * 32;
    const int colbase = blockIdx.x * 128;
    const int tid  = threadIdx.x;
    const int warp = tid >> 5, lane = tid & 31;
    const int wm = warp >> 2;
    const int wn = warp & 3;
    const int g  = lane >> 2, tc = lane & 3;

    float acc[4][4];
    #pragma unroll
    for (int i = 0; i < 4; i++)
        #pragma unroll
        for (int j = 0; j < 4; j++) acc[i][j] = 0.f;

    const int arow = tid >> 3, ak = (tid & 7) * 4;
    const float* Aptr = A + (rowbase + arow) * KTOT + ak;

    float4 aReg = *(const float4*)(Aptr);
    float2 bReg0[4], bReg1[4];
    #pragma unroll
    for (int i = 0; i < 4; i++) {
        int lin = tid + i*256;
        int kk = lin >> 6, c2 = (lin & 63) * 2;
        bReg0[i] = *(const float2*)(W + (2*kk  ) * N + colbase + c2);
        bReg1[i] = *(const float2*)(W + (2*kk+1) * N + colbase + c2);
    }

    const int NCHUNK = KTOT / 32;
    #pragma unroll 1
    for (int ch = 0; ch < NCHUNK; ch++) {
        __syncthreads();
        {
            uint32_t h0 = pack_h2(aReg.x, aReg.y);
            uint32_t h1 = pack_h2(aReg.z, aReg.w);
            *reinterpret_cast<uint2*>(&As[arow][ak]) = make_uint2(h0, h1);
        }
        #pragma unroll
        for (int i = 0; i < 4; i++) {
            int lin = tid + i*256;
            int kk = lin >> 6, c2 = (lin & 63) * 2;
            uint32_t h0 = pack_h2(bReg0[i].x, bReg1[i].x);
            uint32_t h1 = pack_h2(bReg0[i].y, bReg1[i].y);
            *reinterpret_cast<uint2*>(&Bs[kk][c2]) = make_uint2(h0, h1);
        }
        __syncthreads();

        if (ch + 1 < NCHUNK) {
            aReg = *(const float4*)(Aptr + (ch+1)*32);
            #pragma unroll
            for (int i = 0; i < 4; i++) {
                int lin = tid + i*256;
                int kk = lin >> 6, c2 = (lin & 63) * 2;
                bReg0[i] = *(const float2*)(W + ((ch+1)*32 + 2*kk  ) * N + colbase + c2);
                bReg1[i] = *(const float2*)(W + ((ch+1)*32 + 2*kk+1) * N + colbase + c2);
            }
        }

        #pragma unroll
        for (int s = 0; s < 2; s++) {
            const int kc = s*16 + 2*tc;
            uint32_t a0 = *reinterpret_cast<const uint32_t*>(&As[wm*16 + g    ][kc    ]);
            uint32_t a1 = *reinterpret_cast<const uint32_t*>(&As[wm*16 + g + 8][kc    ]);
            uint32_t a2 = *reinterpret_cast<const uint32_t*>(&As[wm*16 + g    ][kc + 8]);
            uint32_t a3 = *reinterpret_cast<const uint32_t*>(&As[wm*16 + g + 8][kc + 8]);
            #pragma unroll
            for (int nt = 0; nt < 4; nt++) {
                int col = wn*32 + nt*8 + g;
                uint32_t b0 = *reinterpret_cast<const uint32_t*>(&Bs[s*8 + tc    ][col]);
                uint32_t b1 = *reinterpret_cast<const uint32_t*>(&Bs[s*8 + tc + 4][col]);
                mma_f16(acc[nt], a0, a1, a2, a3, b0, b1);
            }
        }
    }

    #pragma unroll
    for (int nt = 0; nt < 4; nt++) {
        int col = colbase + wn*32 + nt*8 + 2*tc;
        int r0 = rowbase + wm*16 + g;
        int r1 = r0 + 8;
        float bx = bias[col], by = bias[col+1];
        float2 v0 = make_float2(acc[nt][0] + bx, acc[nt][1] + by);
        float2 v1 = make_float2(acc[nt][2] + bx, acc[nt][3] + by);
        if (res != nullptr) {
            float2 s0 = *(const float2*)(res + r0*N + col);
            float2 s1 = *(const float2*)(res + r1*N + col);
            v0.x += s0.x; v0.y += s0.y;
            v1.x += s1.x; v1.y += s1.y;
        }
        if (RELU) {
            v0.x = fmaxf(v0.x, 0.f); v0.y = fmaxf(v0.y, 0.f);
            v1.x = fmaxf(v1.x, 0.f); v1.y = fmaxf(v1.y, 0.f);
        }
        *(float2*)(out + r0*N + col) = v0;
        *(float2*)(out + r1*N + col) = v1;
    }
}

// =====================================================================
// LN kernels
// =====================================================================
__global__ void __launch_bounds__(128) ln1_cos_kernel(
    const float* __restrict__ pre, const float* __restrict__ w,
    const float* __restrict__ b,   const float* __restrict__ thf)
{
    __shared__ float sS[4], sQ[4];
    const int row = blockIdx.x;
    const int t = threadIdx.x;
    float4 v = ((const float4*)(pre + row*EE))[t];
    float s = v.x + v.y + v.z + v.w;
    float q = v.x*v.x + v.y*v.y + v.z*v.z + v.w*v.w;
    #pragma unroll
    for (int o = 16; o; o >>= 1) {
        s += __shfl_xor_sync(0xffffffffu, s, o);
        q += __shfl_xor_sync(0xffffffffu, q, o);
    }
    if ((t & 31) == 0) { sS[t>>5] = s; sQ[t>>5] = q; }
    __syncthreads();
    s = sS[0] + sS[1] + sS[2] + sS[3];
    q = sQ[0] + sQ[1] + sQ[2] + sQ[3];
    float mu   = s * (1.0f/EE);
    float var  = q * (1.0f/EE) - mu*mu;
    float rstd = rsqrtf(var + 1e-5f);
    float4 lw = ((const float4*)w)[t];
    float4 lb = ((const float4*)b)[t];
    float4 th = ((const float4*)thf)[t];
    float4 x1;
    x1.x = (v.x - mu)*rstd*lw.x + lb.x;
    x1.y = (v.y - mu)*rstd*lw.y + lb.y;
    x1.z = (v.z - mu)*rstd*lw.z + lb.z;
    x1.w = (v.w - mu)*rstd*lw.w + lb.w;
    ((float4*)(g_x1 + row*EE))[t] = x1;
    float4 qf;
    qf.x = __cosf(x1.x)*__cosf(th.x);
    qf.y = __cosf(x1.y)*__cosf(th.y);
    qf.z = __cosf(x1.z)*__cosf(th.z);
    qf.w = __cosf(x1.w)*__cosf(th.w);
    ((float4*)(g_qf + row*EE))[t] = qf;
}

__global__ void __launch_bounds__(128) ln2_kernel(
    const float* __restrict__ pre, const float* __restrict__ w,
    const float* __restrict__ b,   float* __restrict__ out)
{
    __shared__ float sS[4], sQ[4];
    const int row = blockIdx.x;
    const int t = threadIdx.x;
    float4 v = ((const float4*)(pre + row*EE))[t];
    float s = v.x + v.y + v.z + v.w;
    float q = v.x*v.x + v.y*v.y + v.z*v.z + v.w*v.w;
    #pragma unroll
    for (int o = 16; o; o >>= 1) {
        s += __shfl_xor_sync(0xffffffffu, s, o);
        q += __shfl_xor_sync(0xffffffffu, q, o);
    }
    if ((t & 31) == 0) { sS[t>>5] = s; sQ[t>>5] = q; }
    __syncthreads();
    s = sS[0] + sS[1] + sS[2] + sS[3];
    q = sQ[0] + sQ[1] + sQ[2] + sQ[3];
    float mu   = s * (1.0f/EE);
    float var  = q * (1.0f/EE) - mu*mu;
    float rstd = rsqrtf(var + 1e-5f);
    float4 lw = ((const float4*)w)[t];
    float4 lb = ((const float4*)b)[t];
    float4 o4;
    o4.x = (v.x - mu)*rstd*lw.x + lb.x;
    o4.y = (v.y - mu)*rstd*lw.y + lb.y;
    o4.z = (v.z - mu)*rstd*lw.z + lb.z;
    o4.w = (v.w - mu)*rstd*lw.w + lb.w;
    ((float4*)(out + row*EE))[t] = o4;
}

// =====================================================================
extern "C" void kernel_launch(void* const* d_in, const int* in_sizes, int n_in,
                              void* d_out, int out_size) {
    const float* x         = (const float*)d_in[0];
    const float* theta_at  = (const float*)d_in[1];
    const float* w_combine = (const float*)d_in[2];
    const float* b_combine = (const float*)d_in[3];
    const float* theta_ffn = (const float*)d_in[4];
    const float* w1        = (const float*)d_in[5];
    const float* b1        = (const float*)d_in[6];
    const float* w2        = (const float*)d_in[7];
    const float* b2        = (const float*)d_in[8];
    const float* ln1w      = (const float*)d_in[9];
    const float* ln1b      = (const float*)d_in[10];
    const float* ln2w      = (const float*)d_in[11];
    const float* ln2b      = (const float*)d_in[12];
    float* out = (float*)d_out;

    float* d_attn; cudaGetSymbolAddress((void**)&d_attn, g_attn);
    float* d_x1;   cudaGetSymbolAddress((void**)&d_x1,   g_x1);
    float* d_qf;   cudaGetSymbolAddress((void**)&d_qf,   g_qf);
    float* d_hdn;  cudaGetSymbolAddress((void**)&d_hdn,  g_hdn);
    float* d_pre;  cudaGetSymbolAddress((void**)&d_pre,  g_pre);

    // opt-in to 64KB dynamic smem for attention (host attr, capture-safe)
    cudaFuncSetAttribute(attn_mma_kernel,
                         cudaFuncAttributeMaxDynamicSharedMemorySize, ATTN_SMEM);

    qkv_kernel<<<512, 256>>>(x, theta_at);
    attn_mma_kernel<<<1024, 256, ATTN_SMEM>>>();

    mma_gemm_kernel<512, false><<<dim3(4, 64), 256>>>(
        d_attn, w_combine, b_combine, x, d_pre, EE);
    ln1_cos_kernel<<<BS, 128>>>(d_pre, ln1w, ln1b, theta_ffn);

    mma_gemm_kernel<512, true><<<dim3(16, 64), 256>>>(
        d_qf, w1, b1, nullptr, d_hdn, FF);

    mma_gemm_kernel<2048, false><<<dim3(4, 64), 256>>>(
        d_hdn, w2, b2, d_x1, d_pre, EE);
    ln2_kernel<<<BS, 128>>>(d_pre, ln2w, ln2b, out);
}

// round 14
// speedup vs baseline: 1.1176x; 1.1176x over previous
#include <cuda_runtime.h>
#include <cuda_fp16.h>
#include <math.h>
#include <stdint.h>

#define BB 2
#define SS 1024
#define EE 512
#define HH 64
#define DKK 8
#define FF 2048
#define BS (BB*SS)   // 2048

// ---- scratch (device globals: allocation-free) ----
__device__ float   g_q[BB*HH*SS*DKK];    // [B][H][S][8]
__device__ __half  g_attn_h[BS*EE];      // attention out (fp16)
__device__ float   g_x1[BS*EE];          // post-LN1 (f32, ffn2 residual)
__device__ __half  g_qf_h[BS*EE];        // cos(x1)*cos(theta) (fp16)
__device__ __half  g_hdn_h[BS*FF];       // FFN hidden (fp16)
__device__ float   g_pre[BS*EE];         // pre-LN staging (f32)
// pre-packed fp16 weights, k-pair layout: Wh[kk][n] = (W[2kk][n], W[2kk+1][n])
__device__ __half2 g_wch[(EE/2)*EE];     // 256x512
__device__ __half2 g_w1h[(EE/2)*FF];     // 256x2048
__device__ __half2 g_w2h[(FF/2)*EE];     // 1024x512

__device__ __forceinline__ float ex2a(float x) {
    float r; asm("ex2.approx.f32 %0, %1;" : "=f"(r) : "f"(x)); return r;
}
// m16n8k8 tf32 mma (attention)
__device__ __forceinline__ void mma_tf32u(float& c0, float& c1, float& c2, float& c3,
                                          uint32_t A0, uint32_t A1, uint32_t A2, uint32_t A3,
                                          uint32_t B0, uint32_t B1) {
    asm volatile(
        "mma.sync.aligned.m16n8k8.row.col.f32.tf32.tf32.f32 "
        "{%0,%1,%2,%3},{%4,%5,%6,%7},{%8,%9},{%0,%1,%2,%3};"
        : "+f"(c0), "+f"(c1), "+f"(c2), "+f"(c3)
        : "r"(A0), "r"(A1), "r"(A2), "r"(A3), "r"(B0), "r"(B1));
}
// m16n8k16 fp16 mma, f32 accumulate (GEMMs)
__device__ __forceinline__ void mma_f16(float* acc,
                                        uint32_t a0, uint32_t a1, uint32_t a2, uint32_t a3,
                                        uint32_t b0, uint32_t b1) {
    asm volatile(
        "mma.sync.aligned.m16n8k16.row.col.f32.f16.f16.f32 "
        "{%0,%1,%2,%3},{%4,%5,%6,%7},{%8,%9},{%0,%1,%2,%3};"
        : "+f"(acc[0]), "+f"(acc[1]), "+f"(acc[2]), "+f"(acc[3])
        : "r"(a0), "r"(a1), "r"(a2), "r"(a3), "r"(b0), "r"(b1));
}
__device__ __forceinline__ uint32_t pack_h2(float lo, float hi) {
    __half2 h = __floats2half2_rn(lo, hi);
    return *reinterpret_cast<uint32_t*>(&h);
}

// =====================================================================
// K0: weight pre-pack (f32 -> k-pair half2), all three weights, 1 launch
// =====================================================================
#define WC_E ((EE/2)*EE)     // 131072
#define W1_E ((EE/2)*FF)     // 524288
#define W2_E ((FF/2)*EE)     // 524288
__global__ void wpack_kernel(const float* __restrict__ wc,
                             const float* __restrict__ w1,
                             const float* __restrict__ w2) {
    int i = blockIdx.x * 256 + threadIdx.x;
    if (i < WC_E) {
        int kk = i >> 9, n = i & 511;
        g_wch[i] = __floats2half2_rn(wc[(2*kk)*EE + n], wc[(2*kk+1)*EE + n]);
    } else if (i < WC_E + W1_E) {
        int j = i - WC_E;
        int kk = j >> 11, n = j & 2047;
        g_w1h[j] = __floats2half2_rn(w1[(2*kk)*FF + n], w1[(2*kk+1)*FF + n]);
    } else if (i < WC_E + W1_E + W2_E) {
        int j = i - WC_E - W1_E;
        int kk = j >> 9, n = j & 511;
        g_w2h[j] = __floats2half2_rn(w2[(2*kk)*EE + n], w2[(2*kk+1)*EE + n]);
    }
}

// =====================================================================
// K1: ring expvals
// =====================================================================
__global__ void qkv_kernel(const float* __restrict__ x,
                           const float* __restrict__ theta) {
    int i = blockIdx.x * 256 + threadIdx.x;
    int h  = i & (HH-1);
    int bs = i >> 6;
    const float* xp = x + bs*EE + h*DKK;
    float4 xa = *(const float4*)xp;
    float4 xb = *(const float4*)(xp + 4);
    float c0 = __cosf(xa.x + theta[0]);
    float c1 = __cosf(xa.y + theta[1]);
    float c2 = __cosf(xa.z + theta[2]);
    float c3 = __cosf(xa.w + theta[3]);
    float c4 = __cosf(xb.x + theta[4]);
    float c5 = __cosf(xb.y + theta[5]);
    float c6 = __cosf(xb.z + theta[6]);
    float c7 = __cosf(xb.w + theta[7]);
    float o1 = c0*c1;
    float o2 = o1*c2;
    float o3 = o2*c3;
    float o4 = o3*c4;
    float o5 = o4*c5;
    float o6 = o5*c6;
    float o7 = o6*c7;
    float o0 = c1*c2*c3*c4*c5*c6*c7;
    int b = bs >> 10, s = bs & (SS-1);
    float* qp = g_q + (((b*HH + h)*SS) + s)*DKK;
    *(float4*)qp       = make_float4(o0, o1, o2, o3);
    *(float4*)(qp + 4) = make_float4(o4, o5, o6, o7);
}

// =====================================================================
// K2: tensor-core attention (R10 exact form: dual-strip tf32, all-MUFU,
// token-permuted zero-shuffle layout). Epilogue stores fp16.
// =====================================================================
__global__ void __launch_bounds__(256, 4) attn_mma_kernel() {
    __shared__ float Ks[SS*12];       // 48 KB, row stride 12
    const int bh   = blockIdx.x >> 3;
    const int tile = blockIdx.x & 7;

    const float* qsrc = g_q + bh*(SS*DKK);
    for (int j = threadIdx.x; j < SS*DKK/4; j += 256) {
        float4 v = ((const float4*)qsrc)[j];
        int t = j >> 1, hf = (j & 1) * 4;
        *(float4*)&Ks[t*12 + hf] = v;
    }
    __syncthreads();

    const int lane = threadIdx.x & 31, warp = threadIdx.x >> 5;
    const int g = lane >> 2, tc = lane & 3;
    const int sg = (g >> 1) + (g & 1)*4;     // sigma(g)
    const int row0 = tile*128 + warp*16;

    const float SCL = 0.35355339059f * 1.44269504089f;   // 1/sqrt(8)*log2(e)
    const uint32_t qa0 = __float_as_uint(Ks[(row0+g  )*12 + tc  ] * SCL);
    const uint32_t qa1 = __float_as_uint(Ks[(row0+g+8)*12 + tc  ] * SCL);
    const uint32_t qa2 = __float_as_uint(Ks[(row0+g  )*12 + tc+4] * SCL);
    const uint32_t qa3 = __float_as_uint(Ks[(row0+g+8)*12 + tc+4] * SCL);

    float oa0=0.f, oa1=0.f, oa2=0.f, oa3=0.f;
    float ob0=0.f, ob1=0.f, ob2=0.f, ob3=0.f;
    float ra0=0.f, ra1=0.f, rb0=0.f, rb1=0.f;

    #pragma unroll 2
    for (int t0 = 0; t0 < SS; t0 += 16) {
        const int tA = t0, tB = t0 + 8;
        uint32_t sA0 = __float_as_uint(Ks[(tA+sg)*12 + tc  ]);
        uint32_t sA1 = __float_as_uint(Ks[(tA+sg)*12 + tc+4]);
        uint32_t sB0 = __float_as_uint(Ks[(tB+sg)*12 + tc  ]);
        uint32_t sB1 = __float_as_uint(Ks[(tB+sg)*12 + tc+4]);
        float a0=0.f,a1=0.f,a2=0.f,a3=0.f;
        float b0=0.f,b1=0.f,b2=0.f,b3=0.f;
        mma_tf32u(a0,a1,a2,a3, qa0,qa1,qa2,qa3, sA0,sA1);
        mma_tf32u(b0,b1,b2,b3, qa0,qa1,qa2,qa3, sB0,sB1);

        float pA0 = ex2a(a0), pA1 = ex2a(a1), pA2 = ex2a(a2), pA3 = ex2a(a3);
        float pB0 = ex2a(b0), pB1 = ex2a(b1), pB2 = ex2a(b2), pB3 = ex2a(b3);
        ra0 += pA0 + pA1;  ra1 += pA2 + pA3;
        rb0 += pB0 + pB1;  rb1 += pB2 + pB3;

        uint32_t vA0 = __float_as_uint(Ks[(tA+tc  )*12 + g]);
        uint32_t vA1 = __float_as_uint(Ks[(tA+tc+4)*12 + g]);
        uint32_t vB0 = __float_as_uint(Ks[(tB+tc  )*12 + g]);
        uint32_t vB1 = __float_as_uint(Ks[(tB+tc+4)*12 + g]);
        mma_tf32u(oa0,oa1,oa2,oa3,
                  __float_as_uint(pA0), __float_as_uint(pA2),
                  __float_as_uint(pA1), __float_as_uint(pA3), vA0, vA1);
        mma_tf32u(ob0,ob1,ob2,ob3,
                  __float_as_uint(pB0), __float_as_uint(pB2),
                  __float_as_uint(pB1), __float_as_uint(pB3), vB0, vB1);
    }

    float rs0 = ra0 + rb0, rs1 = ra1 + rb1;
    rs0 += __shfl_xor_sync(0xffffffffu, rs0, 1);
    rs0 += __shfl_xor_sync(0xffffffffu, rs0, 2);
    rs1 += __shfl_xor_sync(0xffffffffu, rs1, 1);
    rs1 += __shfl_xor_sync(0xffffffffu, rs1, 2);
    float i0 = 1.0f / rs0, i1 = 1.0f / rs1;

    const int b = bh >> 6, h = bh & (HH-1);
    const int r0 = row0 + g, r1 = r0 + 8;
    uint32_t h0 = pack_h2((oa0+ob0)*i0, (oa1+ob1)*i0);
    uint32_t h1 = pack_h2((oa2+ob2)*i1, (oa3+ob3)*i1);
    *reinterpret_cast<uint32_t*>(g_attn_h + (b*SS + r0)*EE + h*DKK + 2*tc) = h0;
    *reinterpret_cast<uint32_t*>(g_attn_h + (b*SS + r1)*EE + h*DKK + 2*tc) = h1;
}

// =====================================================================
// fp16 m16n8k16 GEMM, fp16 operands in memory: A half [row][KTOT],
// Wh half2 k-pair [kk][N]. Staging = raw uint2 copies (no conversion).
// block tile 32x128, 8 warps (2M x 4N), warp tile 16x32.
// =====================================================================
template<int KTOT, bool RELU, bool OUTH>
__global__ void __launch_bounds__(256) mma_gemm_kernel(
    const __half* __restrict__ A, const __half2* __restrict__ Wh,
    const float* __restrict__ bias, const float* __restrict__ res,
    float* __restrict__ outf, __half* __restrict__ outh, int N)
{
    __shared__ __half As[32][40];
    __shared__ __half2 Bs[16][136];

    const int rowbase = blockIdx.y * 32;
    const int colbase = blockIdx.x * 128;
    const int tid  = threadIdx.x;
    const int warp = tid >> 5, lane = tid & 31;
    const int wm = warp >> 2;
    const int wn = warp & 3;
    const int g  = lane >> 2, tc = lane & 3;

    float acc[4][4];
    #pragma unroll
    for (int i = 0; i < 4; i++)
        #pragma unroll
        for (int j = 0; j < 4; j++) acc[i][j] = 0.f;

    // A staging: thread -> (row, 4 k-halves)
    const int arow = tid >> 3, ak = (tid & 7) * 4;
    const __half* Aptr = A + (rowbase + arow) * KTOT + ak;
    // B staging: 4 uint2 per thread; lin -> (kk, 2 half2 cols)
    uint2 aReg = *(const uint2*)(Aptr);
    uint2 bReg[4];
    #pragma unroll
    for (int i = 0; i < 4; i++) {
        int lin = tid + i*256;
        int kk = lin >> 6, u2 = (lin & 63) * 2;
        bReg[i] = *(const uint2*)(Wh + kk * N + colbase + u2);
    }

    const int NCHUNK = KTOT / 32;
    #pragma unroll 1
    for (int ch = 0; ch < NCHUNK; ch++) {
        __syncthreads();
        *reinterpret_cast<uint2*>(&As[arow][ak]) = aReg;
        #pragma unroll
        for (int i = 0; i < 4; i++) {
            int lin = tid + i*256;
            int kk = lin >> 6, u2 = (lin & 63) * 2;
            *reinterpret_cast<uint2*>(&Bs[kk][u2]) = bReg[i];
        }
        __syncthreads();

        if (ch + 1 < NCHUNK) {
            aReg = *(const uint2*)(Aptr + (ch+1)*32);
            #pragma unroll
            for (int i = 0; i < 4; i++) {
                int lin = tid + i*256;
                int kk = lin >> 6, u2 = (lin & 63) * 2;
                bReg[i] = *(const uint2*)(Wh + ((ch+1)*16 + kk) * N + colbase + u2);
            }
        }

        #pragma unroll
        for (int s = 0; s < 2; s++) {
            const int kc = s*16 + 2*tc;
            uint32_t a0 = *reinterpret_cast<const uint32_t*>(&As[wm*16 + g    ][kc    ]);
            uint32_t a1 = *reinterpret_cast<const uint32_t*>(&As[wm*16 + g + 8][kc    ]);
            uint32_t a2 = *reinterpret_cast<const uint32_t*>(&As[wm*16 + g    ][kc + 8]);
            uint32_t a3 = *reinterpret_cast<const uint32_t*>(&As[wm*16 + g + 8][kc + 8]);
            #pragma unroll
            for (int nt = 0; nt < 4; nt++) {
                int col = wn*32 + nt*8 + g;
                uint32_t b0 = *reinterpret_cast<const uint32_t*>(&Bs[s*8 + tc    ][col]);
                uint32_t b1 = *reinterpret_cast<const uint32_t*>(&Bs[s*8 + tc + 4][col]);
                mma_f16(acc[nt], a0, a1, a2, a3, b0, b1);
            }
        }
    }

    #pragma unroll
    for (int nt = 0; nt < 4; nt++) {
        int col = colbase + wn*32 + nt*8 + 2*tc;
        int r0 = rowbase + wm*16 + g;
        int r1 = r0 + 8;
        float bx = bias[col], by = bias[col+1];
        float2 v0 = make_float2(acc[nt][0] + bx, acc[nt][1] + by);
        float2 v1 = make_float2(acc[nt][2] + bx, acc[nt][3] + by);
        if (res != nullptr) {
            float2 s0 = *(const float2*)(res + r0*N + col);
            float2 s1 = *(const float2*)(res + r1*N + col);
            v0.x += s0.x; v0.y += s0.y;
            v1.x += s1.x; v1.y += s1.y;
        }
        if (RELU) {
            v0.x = fmaxf(v0.x, 0.f); v0.y = fmaxf(v0.y, 0.f);
            v1.x = fmaxf(v1.x, 0.f); v1.y = fmaxf(v1.y, 0.f);
        }
        if (OUTH) {
            *reinterpret_cast<uint32_t*>(outh + r0*N + col) = pack_h2(v0.x, v0.y);
            *reinterpret_cast<uint32_t*>(outh + r1*N + col) = pack_h2(v1.x, v1.y);
        } else {
            *(float2*)(outf + r0*N + col) = v0;
            *(float2*)(outf + r1*N + col) = v1;
        }
    }
}

// =====================================================================
// LN kernels
// =====================================================================
__global__ void __launch_bounds__(128) ln1_cos_kernel(
    const float* __restrict__ pre, const float* __restrict__ w,
    const float* __restrict__ b,   const float* __restrict__ thf)
{
    __shared__ float sS[4], sQ[4];
    const int row = blockIdx.x;
    const int t = threadIdx.x;
    float4 v = ((const float4*)(pre + row*EE))[t];
    float s = v.x + v.y + v.z + v.w;
    float q = v.x*v.x + v.y*v.y + v.z*v.z + v.w*v.w;
    #pragma unroll
    for (int o = 16; o; o >>= 1) {
        s += __shfl_xor_sync(0xffffffffu, s, o);
        q += __shfl_xor_sync(0xffffffffu, q, o);
    }
    if ((t & 31) == 0) { sS[t>>5] = s; sQ[t>>5] = q; }
    __syncthreads();
    s = sS[0] + sS[1] + sS[2] + sS[3];
    q = sQ[0] + sQ[1] + sQ[2] + sQ[3];
    float mu   = s * (1.0f/EE);
    float var  = q * (1.0f/EE) - mu*mu;
    float rstd = rsqrtf(var + 1e-5f);
    float4 lw = ((const float4*)w)[t];
    float4 lb = ((const float4*)b)[t];
    float4 th = ((const float4*)thf)[t];
    float4 x1;
    x1.x = (v.x - mu)*rstd*lw.x + lb.x;
    x1.y = (v.y - mu)*rstd*lw.y + lb.y;
    x1.z = (v.z - mu)*rstd*lw.z + lb.z;
    x1.w = (v.w - mu)*rstd*lw.w + lb.w;
    ((float4*)(g_x1 + row*EE))[t] = x1;
    float qx = __cosf(x1.x)*__cosf(th.x);
    float qy = __cosf(x1.y)*__cosf(th.y);
    float qz = __cosf(x1.z)*__cosf(th.z);
    float qw = __cosf(x1.w)*__cosf(th.w);
    *reinterpret_cast<uint2*>(g_qf_h + row*EE + t*4) =
        make_uint2(pack_h2(qx, qy), pack_h2(qz, qw));
}

__global__ void __launch_bounds__(128) ln2_kernel(
    const float* __restrict__ pre, const float* __restrict__ w,
    const float* __restrict__ b,   float* __restrict__ out)
{
    __shared__ float sS[4], sQ[4];
    const int row = blockIdx.x;
    const int t = threadIdx.x;
    float4 v = ((const float4*)(pre + row*EE))[t];
    float s = v.x + v.y + v.z + v.w;
    float q = v.x*v.x + v.y*v.y + v.z*v.z + v.w*v.w;
    #pragma unroll
    for (int o = 16; o; o >>= 1) {
        s += __shfl_xor_sync(0xffffffffu, s, o);
        q += __shfl_xor_sync(0xffffffffu, q, o);
    }
    if ((t & 31) == 0) { sS[t>>5] = s; sQ[t>>5] = q; }
    __syncthreads();
    s = sS[0] + sS[1] + sS[2] + sS[3];
    q = sQ[0] + sQ[1] + sQ[2] + sQ[3];
    float mu   = s * (1.0f/EE);
    float var  = q * (1.0f/EE) - mu*mu;
    float rstd = rsqrtf(var + 1e-5f);
    float4 lw = ((const float4*)w)[t];
    float4 lb = ((const float4*)b)[t];
    float4 o4;
    o4.x = (v.x - mu)*rstd*lw.x + lb.x;
    o4.y = (v.y - mu)*rstd*lw.y + lb.y;
    o4.z = (v.z - mu)*rstd*lw.z + lb.z;
    o4.w = (v.w - mu)*rstd*lw.w + lb.w;
    ((float4*)(out + row*EE))[t] = o4;
}

// =====================================================================
extern "C" void kernel_launch(void* const* d_in, const int* in_sizes, int n_in,
                              void* d_out, int out_size) {
    const float* x         = (const float*)d_in[0];
    const float* theta_at  = (const float*)d_in[1];
    const float* w_combine = (const float*)d_in[2];
    const float* b_combine = (const float*)d_in[3];
    const float* theta_ffn = (const float*)d_in[4];
    const float* w1        = (const float*)d_in[5];
    const float* b1        = (const float*)d_in[6];
    const float* w2        = (const float*)d_in[7];
    const float* b2        = (const float*)d_in[8];
    const float* ln1w      = (const float*)d_in[9];
    const float* ln1b      = (const float*)d_in[10];
    const float* ln2w      = (const float*)d_in[11];
    const float* ln2b      = (const float*)d_in[12];
    float* out = (float*)d_out;

    __half* d_attn_h; cudaGetSymbolAddress((void**)&d_attn_h, g_attn_h);
    float*  d_x1;     cudaGetSymbolAddress((void**)&d_x1,     g_x1);
    __half* d_qf_h;   cudaGetSymbolAddress((void**)&d_qf_h,   g_qf_h);
    __half* d_hdn_h;  cudaGetSymbolAddress((void**)&d_hdn_h,  g_hdn_h);
    float*  d_pre;    cudaGetSymbolAddress((void**)&d_pre,    g_pre);
    __half2* d_wch;   cudaGetSymbolAddress((void**)&d_wch,    g_wch);
    __half2* d_w1h;   cudaGetSymbolAddress((void**)&d_w1h,    g_w1h);
    __half2* d_w2h;   cudaGetSymbolAddress((void**)&d_w2h,    g_w2h);

    const int WTOT = WC_E + W1_E + W2_E;
    wpack_kernel<<<(WTOT + 255)/256, 256>>>(w_combine, w1, w2);
    qkv_kernel<<<512, 256>>>(x, theta_at);
    attn_mma_kernel<<<1024, 256>>>();

    // combine: g_attn_h[2048,512] @ wch + bias + x -> g_pre (f32)
    mma_gemm_kernel<512, false, false><<<dim3(4, 64), 256>>>(
        d_attn_h, d_wch, b_combine, x, d_pre, nullptr, EE);
    ln1_cos_kernel<<<BS, 128>>>(d_pre, ln1w, ln1b, theta_ffn);

    // ffn1: g_qf_h @ w1h + b1, relu -> g_hdn_h (fp16)
    mma_gemm_kernel<512, true, true><<<dim3(16, 64), 256>>>(
        d_qf_h, d_w1h, b1, nullptr, nullptr, d_hdn_h, FF);

    // ffn2: g_hdn_h @ w2h + b2 + g_x1 -> g_pre (f32)
    mma_gemm_kernel<2048, false, false><<<dim3(4, 64), 256>>>(
        d_hdn_h, d_w2h, b2, d_x1, d_pre, nullptr, EE);
    ln2_kernel<<<BS, 128>>>(d_pre, ln2w, ln2b, out);
}

// round 15
// speedup vs baseline: 1.1491x; 1.0281x over previous
#include <cuda_runtime.h>
#include <cuda_fp16.h>
#include <math.h>
#include <stdint.h>

#define BB 2
#define SS 1024
#define EE 512
#define HH 64
#define DKK 8
#define FF 2048
#define BS (BB*SS)   // 2048

// ---- scratch (device globals: allocation-free) ----
__device__ float   g_q[BB*HH*SS*DKK];    // [B][H][S][8]
__device__ __half  g_attn_h[BS*EE];      // attention out (fp16)
__device__ float   g_x1[BS*EE];          // post-LN1 (f32, ffn2 residual)
__device__ __half  g_qf_h[BS*EE];        // cos(x1)*cos(theta) (fp16)
__device__ __half  g_hdn_h[BS*FF];       // FFN hidden (fp16)
__device__ float   g_pre4[4*BS*EE];      // split-K partials (4 x 4MB)
// pre-packed fp16 weights, k-pair layout: Wh[kk][n] = (W[2kk][n], W[2kk+1][n])
__device__ __half2 g_wch[(EE/2)*EE];     // 256x512
__device__ __half2 g_w1h[(EE/2)*FF];     // 256x2048
__device__ __half2 g_w2h[(FF/2)*EE];     // 1024x512

__device__ __forceinline__ float ex2a(float x) {
    float r; asm("ex2.approx.f32 %0, %1;" : "=f"(r) : "f"(x)); return r;
}
// m16n8k8 tf32 mma (attention)
__device__ __forceinline__ void mma_tf32u(float& c0, float& c1, float& c2, float& c3,
                                          uint32_t A0, uint32_t A1, uint32_t A2, uint32_t A3,
                                          uint32_t B0, uint32_t B1) {
    asm volatile(
        "mma.sync.aligned.m16n8k8.row.col.f32.tf32.tf32.f32 "
        "{%0,%1,%2,%3},{%4,%5,%6,%7},{%8,%9},{%0,%1,%2,%3};"
        : "+f"(c0), "+f"(c1), "+f"(c2), "+f"(c3)
        : "r"(A0), "r"(A1), "r"(A2), "r"(A3), "r"(B0), "r"(B1));
}
// m16n8k16 fp16 mma, f32 accumulate (GEMMs)
__device__ __forceinline__ void mma_f16(float* acc,
                                        uint32_t a0, uint32_t a1, uint32_t a2, uint32_t a3,
                                        uint32_t b0, uint32_t b1) {
    asm volatile(
        "mma.sync.aligned.m16n8k16.row.col.f32.f16.f16.f32 "
        "{%0,%1,%2,%3},{%4,%5,%6,%7},{%8,%9},{%0,%1,%2,%3};"
        : "+f"(acc[0]), "+f"(acc[1]), "+f"(acc[2]), "+f"(acc[3])
        : "r"(a0), "r"(a1), "r"(a2), "r"(a3), "r"(b0), "r"(b1));
}
__device__ __forceinline__ uint32_t pack_h2(float lo, float hi) {
    __half2 h = __floats2half2_rn(lo, hi);
    return *reinterpret_cast<uint32_t*>(&h);
}

// =====================================================================
// K0: weight pre-pack (f32 -> k-pair half2)
// =====================================================================
#define WC_E ((EE/2)*EE)     // 131072
#define W1_E ((EE/2)*FF)     // 524288
#define W2_E ((FF/2)*EE)     // 524288
__global__ void wpack_kernel(const float* __restrict__ wc,
                             const float* __restrict__ w1,
                             const float* __restrict__ w2) {
    int i = blockIdx.x * 256 + threadIdx.x;
    if (i < WC_E) {
        int kk = i >> 9, n = i & 511;
        g_wch[i] = __floats2half2_rn(wc[(2*kk)*EE + n], wc[(2*kk+1)*EE + n]);
    } else if (i < WC_E + W1_E) {
        int j = i - WC_E;
        int kk = j >> 11, n = j & 2047;
        g_w1h[j] = __floats2half2_rn(w1[(2*kk)*FF + n], w1[(2*kk+1)*FF + n]);
    } else if (i < WC_E + W1_E + W2_E) {
        int j = i - WC_E - W1_E;
        int kk = j >> 9, n = j & 511;
        g_w2h[j] = __floats2half2_rn(w2[(2*kk)*EE + n], w2[(2*kk+1)*EE + n]);
    }
}

// =====================================================================
// K1: ring expvals
// =====================================================================
__global__ void qkv_kernel(const float* __restrict__ x,
                           const float* __restrict__ theta) {
    int i = blockIdx.x * 256 + threadIdx.x;
    int h  = i & (HH-1);
    int bs = i >> 6;
    const float* xp = x + bs*EE + h*DKK;
    float4 xa = *(const float4*)xp;
    float4 xb = *(const float4*)(xp + 4);
    float c0 = __cosf(xa.x + theta[0]);
    float c1 = __cosf(xa.y + theta[1]);
    float c2 = __cosf(xa.z + theta[2]);
    float c3 = __cosf(xa.w + theta[3]);
    float c4 = __cosf(xb.x + theta[4]);
    float c5 = __cosf(xb.y + theta[5]);
    float c6 = __cosf(xb.z + theta[6]);
    float c7 = __cosf(xb.w + theta[7]);
    float o1 = c0*c1;
    float o2 = o1*c2;
    float o3 = o2*c3;
    float o4 = o3*c4;
    float o5 = o4*c5;
    float o6 = o5*c6;
    float o7 = o6*c7;
    float o0 = c1*c2*c3*c4*c5*c6*c7;
    int b = bs >> 10, s = bs & (SS-1);
    float* qp = g_q + (((b*HH + h)*SS) + s)*DKK;
    *(float4*)qp       = make_float4(o0, o1, o2, o3);
    *(float4*)(qp + 4) = make_float4(o4, o5, o6, o7);
}

// =====================================================================
// K2: tensor-core attention (R10/R14 form, fp16 epilogue)
// =====================================================================
__global__ void __launch_bounds__(256, 4) attn_mma_kernel() {
    __shared__ float Ks[SS*12];       // 48 KB, row stride 12
    const int bh   = blockIdx.x >> 3;
    const int tile = blockIdx.x & 7;

    const float* qsrc = g_q + bh*(SS*DKK);
    for (int j = threadIdx.x; j < SS*DKK/4; j += 256) {
        float4 v = ((const float4*)qsrc)[j];
        int t = j >> 1, hf = (j & 1) * 4;
        *(float4*)&Ks[t*12 + hf] = v;
    }
    __syncthreads();

    const int lane = threadIdx.x & 31, warp = threadIdx.x >> 5;
    const int g = lane >> 2, tc = lane & 3;
    const int sg = (g >> 1) + (g & 1)*4;     // sigma(g)
    const int row0 = tile*128 + warp*16;

    const float SCL = 0.35355339059f * 1.44269504089f;   // 1/sqrt(8)*log2(e)
    const uint32_t qa0 = __float_as_uint(Ks[(row0+g  )*12 + tc  ] * SCL);
    const uint32_t qa1 = __float_as_uint(Ks[(row0+g+8)*12 + tc  ] * SCL);
    const uint32_t qa2 = __float_as_uint(Ks[(row0+g  )*12 + tc+4] * SCL);
    const uint32_t qa3 = __float_as_uint(Ks[(row0+g+8)*12 + tc+4] * SCL);

    float oa0=0.f, oa1=0.f, oa2=0.f, oa3=0.f;
    float ob0=0.f, ob1=0.f, ob2=0.f, ob3=0.f;
    float ra0=0.f, ra1=0.f, rb0=0.f, rb1=0.f;

    #pragma unroll 2
    for (int t0 = 0; t0 < SS; t0 += 16) {
        const int tA = t0, tB = t0 + 8;
        uint32_t sA0 = __float_as_uint(Ks[(tA+sg)*12 + tc  ]);
        uint32_t sA1 = __float_as_uint(Ks[(tA+sg)*12 + tc+4]);
        uint32_t sB0 = __float_as_uint(Ks[(tB+sg)*12 + tc  ]);
        uint32_t sB1 = __float_as_uint(Ks[(tB+sg)*12 + tc+4]);
        float a0=0.f,a1=0.f,a2=0.f,a3=0.f;
        float b0=0.f,b1=0.f,b2=0.f,b3=0.f;
        mma_tf32u(a0,a1,a2,a3, qa0,qa1,qa2,qa3, sA0,sA1);
        mma_tf32u(b0,b1,b2,b3, qa0,qa1,qa2,qa3, sB0,sB1);

        float pA0 = ex2a(a0), pA1 = ex2a(a1), pA2 = ex2a(a2), pA3 = ex2a(a3);
        float pB0 = ex2a(b0), pB1 = ex2a(b1), pB2 = ex2a(b2), pB3 = ex2a(b3);
        ra0 += pA0 + pA1;  ra1 += pA2 + pA3;
        rb0 += pB0 + pB1;  rb1 += pB2 + pB3;

        uint32_t vA0 = __float_as_uint(Ks[(tA+tc  )*12 + g]);
        uint32_t vA1 = __float_as_uint(Ks[(tA+tc+4)*12 + g]);
        uint32_t vB0 = __float_as_uint(Ks[(tB+tc  )*12 + g]);
        uint32_t vB1 = __float_as_uint(Ks[(tB+tc+4)*12 + g]);
        mma_tf32u(oa0,oa1,oa2,oa3,
                  __float_as_uint(pA0), __float_as_uint(pA2),
                  __float_as_uint(pA1), __float_as_uint(pA3), vA0, vA1);
        mma_tf32u(ob0,ob1,ob2,ob3,
                  __float_as_uint(pB0), __float_as_uint(pB2),
                  __float_as_uint(pB1), __float_as_uint(pB3), vB0, vB1);
    }

    float rs0 = ra0 + rb0, rs1 = ra1 + rb1;
    rs0 += __shfl_xor_sync(0xffffffffu, rs0, 1);
    rs0 += __shfl_xor_sync(0xffffffffu, rs0, 2);
    rs1 += __shfl_xor_sync(0xffffffffu, rs1, 1);
    rs1 += __shfl_xor_sync(0xffffffffu, rs1, 2);
    float i0 = 1.0f / rs0, i1 = 1.0f / rs1;

    const int b = bh >> 6, h = bh & (HH-1);
    const int r0 = row0 + g, r1 = r0 + 8;
    *reinterpret_cast<uint32_t*>(g_attn_h + (b*SS + r0)*EE + h*DKK + 2*tc)
        = pack_h2((oa0+ob0)*i0, (oa1+ob1)*i0);
    *reinterpret_cast<uint32_t*>(g_attn_h + (b*SS + r1)*EE + h*DKK + 2*tc)
        = pack_h2((oa2+ob2)*i1, (oa3+ob3)*i1);
}

// =====================================================================
// Split-K fp16 GEMM: partial[split][row][col] = A[row][ksplit-range] @ W
// grid (N/128, M/32, 4). Raw f32 partial output; bias/residual in LN.
// =====================================================================
template<int KCH>
__global__ void __launch_bounds__(256) mma_gemm_split_kernel(
    const __half* __restrict__ A, const __half2* __restrict__ Wh,
    float* __restrict__ partial, int N, int KTOT)
{
    __shared__ __half As[32][40];
    __shared__ __half2 Bs[16][136];

    const int rowbase = blockIdx.y * 32;
    const int colbase = blockIdx.x * 128;
    const int ks      = blockIdx.z;           // split index
    const int tid  = threadIdx.x;
    const int warp = tid >> 5, lane = tid & 31;
    const int wm = warp >> 2;
    const int wn = warp & 3;
    const int g  = lane >> 2, tc = lane & 3;

    const __half2* Wp = Wh + (ks * (KCH/2)) * N;
    float* outp = partial + ks * (BS * N);

    float acc[4][4];
    #pragma unroll
    for (int i = 0; i < 4; i++)
        #pragma unroll
        for (int j = 0; j < 4; j++) acc[i][j] = 0.f;

    const int arow = tid >> 3, ak = (tid & 7) * 4;
    const __half* Aptr = A + (rowbase + arow) * KTOT + ks * KCH + ak;

    uint2 aReg = *(const uint2*)(Aptr);
    uint2 bReg[4];
    #pragma unroll
    for (int i = 0; i < 4; i++) {
        int lin = tid + i*256;
        int kk = lin >> 6, u2 = (lin & 63) * 2;
        bReg[i] = *(const uint2*)(Wp + kk * N + colbase + u2);
    }

    const int NCHUNK = KCH / 32;
    #pragma unroll 1
    for (int ch = 0; ch < NCHUNK; ch++) {
        __syncthreads();
        *reinterpret_cast<uint2*>(&As[arow][ak]) = aReg;
        #pragma unroll
        for (int i = 0; i < 4; i++) {
            int lin = tid + i*256;
            int kk = lin >> 6, u2 = (lin & 63) * 2;
            *reinterpret_cast<uint2*>(&Bs[kk][u2]) = bReg[i];
        }
        __syncthreads();

        if (ch + 1 < NCHUNK) {
            aReg = *(const uint2*)(Aptr + (ch+1)*32);
            #pragma unroll
            for (int i = 0; i < 4; i++) {
                int lin = tid + i*256;
                int kk = lin >> 6, u2 = (lin & 63) * 2;
                bReg[i] = *(const uint2*)(Wp + ((ch+1)*16 + kk) * N + colbase + u2);
            }
        }

        #pragma unroll
        for (int s = 0; s < 2; s++) {
            const int kc = s*16 + 2*tc;
            uint32_t a0 = *reinterpret_cast<const uint32_t*>(&As[wm*16 + g    ][kc    ]);
            uint32_t a1 = *reinterpret_cast<const uint32_t*>(&As[wm*16 + g + 8][kc    ]);
            uint32_t a2 = *reinterpret_cast<const uint32_t*>(&As[wm*16 + g    ][kc + 8]);
            uint32_t a3 = *reinterpret_cast<const uint32_t*>(&As[wm*16 + g + 8][kc + 8]);
            #pragma unroll
            for (int nt = 0; nt < 4; nt++) {
                int col = wn*32 + nt*8 + g;
                uint32_t b0 = *reinterpret_cast<const uint32_t*>(&Bs[s*8 + tc    ][col]);
                uint32_t b1 = *reinterpret_cast<const uint32_t*>(&Bs[s*8 + tc + 4][col]);
                mma_f16(acc[nt], a0, a1, a2, a3, b0, b1);
            }
        }
    }

    #pragma unroll
    for (int nt = 0; nt < 4; nt++) {
        int col = colbase + wn*32 + nt*8 + 2*tc;
        int r0 = rowbase + wm*16 + g;
        int r1 = r0 + 8;
        *(float2*)(outp + r0*N + col) = make_float2(acc[nt][0], acc[nt][1]);
        *(float2*)(outp + r1*N + col) = make_float2(acc[nt][2], acc[nt][3]);
    }
}

// =====================================================================
// ffn1: full-K fp16 GEMM with bias+relu, fp16 out (R14 form, grid 1024)
// =====================================================================
__global__ void __launch_bounds__(256) mma_gemm_ffn1_kernel(
    const __half* __restrict__ A, const __half2* __restrict__ Wh,
    const float* __restrict__ bias, __half* __restrict__ outh, int N)
{
    __shared__ __half As[32][40];
    __shared__ __half2 Bs[16][136];

    const int rowbase = blockIdx.y * 32;
    const int colbase = blockIdx.x * 128;
    const int tid  = threadIdx.x;
    const int warp = tid >> 5, lane = tid & 31;
    const int wm = warp >> 2;
    const int wn = warp & 3;
    const int g  = lane >> 2, tc = lane & 3;
    const int KTOT = 512;

    float acc[4][4];
    #pragma unroll
    for (int i = 0; i < 4; i++)
        #pragma unroll
        for (int j = 0; j < 4; j++) acc[i][j] = 0.f;

    const int arow = tid >> 3, ak = (tid & 7) * 4;
    const __half* Aptr = A + (rowbase + arow) * KTOT + ak;

    uint2 aReg = *(const uint2*)(Aptr);
    uint2 bReg[4];
    #pragma unroll
    for (int i = 0; i < 4; i++) {
        int lin = tid + i*256;
        int kk = lin >> 6, u2 = (lin & 63) * 2;
        bReg[i] = *(const uint2*)(Wh + kk * N + colbase + u2);
    }

    const int NCHUNK = KTOT / 32;
    #pragma unroll 1
    for (int ch = 0; ch < NCHUNK; ch++) {
        __syncthreads();
        *reinterpret_cast<uint2*>(&As[arow][ak]) = aReg;
        #pragma unroll
        for (int i = 0; i < 4; i++) {
            int lin = tid + i*256;
            int kk = lin >> 6, u2 = (lin & 63) * 2;
            *reinterpret_cast<uint2*>(&Bs[kk][u2]) = bReg[i];
        }
        __syncthreads();

        if (ch + 1 < NCHUNK) {
            aReg = *(const uint2*)(Aptr + (ch+1)*32);
            #pragma unroll
            for (int i = 0; i < 4; i++) {
                int lin = tid + i*256;
                int kk = lin >> 6, u2 = (lin & 63) * 2;
                bReg[i] = *(const uint2*)(Wh + ((ch+1)*16 + kk) * N + colbase + u2);
            }
        }

        #pragma unroll
        for (int s = 0; s < 2; s++) {
            const int kc = s*16 + 2*tc;
            uint32_t a0 = *reinterpret_cast<const uint32_t*>(&As[wm*16 + g    ][kc    ]);
            uint32_t a1 = *reinterpret_cast<const uint32_t*>(&As[wm*16 + g + 8][kc    ]);
            uint32_t a2 = *reinterpret_cast<const uint32_t*>(&As[wm*16 + g    ][kc + 8]);
            uint32_t a3 = *reinterpret_cast<const uint32_t*>(&As[wm*16 + g + 8][kc + 8]);
            #pragma unroll
            for (int nt = 0; nt < 4; nt++) {
                int col = wn*32 + nt*8 + g;
                uint32_t b0 = *reinterpret_cast<const uint32_t*>(&Bs[s*8 + tc    ][col]);
                uint32_t b1 = *reinterpret_cast<const uint32_t*>(&Bs[s*8 + tc + 4][col]);
                mma_f16(acc[nt], a0, a1, a2, a3, b0, b1);
            }
        }
    }

    #pragma unroll
    for (int nt = 0; nt < 4; nt++) {
        int col = colbase + wn*32 + nt*8 + 2*tc;
        int r0 = rowbase + wm*16 + g;
        int r1 = r0 + 8;
        float bx = bias[col], by = bias[col+1];
        float v00 = fmaxf(acc[nt][0] + bx, 0.f);
        float v01 = fmaxf(acc[nt][1] + by, 0.f);
        float v10 = fmaxf(acc[nt][2] + bx, 0.f);
        float v11 = fmaxf(acc[nt][3] + by, 0.f);
        *reinterpret_cast<uint32_t*>(outh + r0*N + col) = pack_h2(v00, v01);
        *reinterpret_cast<uint32_t*>(outh + r1*N + col) = pack_h2(v10, v11);
    }
}

// =====================================================================
// LN kernels: sum 4 split-K partials + bias + residual, then LN
// =====================================================================
__global__ void __launch_bounds__(128) ln1_cos_kernel(
    const float* __restrict__ part, const float* __restrict__ bias,
    const float* __restrict__ x,
    const float* __restrict__ w,  const float* __restrict__ b,
    const float* __restrict__ thf)
{
    __shared__ float sS[4], sQ[4];
    const int row = blockIdx.x;
    const int t = threadIdx.x;
    float4 p0 = ((const float4*)(part + 0*BS*EE + row*EE))[t];
    float4 p1 = ((const float4*)(part + 1*BS*EE + row*EE))[t];
    float4 p2 = ((const float4*)(part + 2*BS*EE + row*EE))[t];
    float4 p3 = ((const float4*)(part + 3*BS*EE + row*EE))[t];
    float4 bb = ((const float4*)bias)[t];
    float4 xv = ((const float4*)(x + row*EE))[t];
    float4 v;
    v.x = (p0.x + p1.x) + (p2.x + p3.x) + bb.x + xv.x;
    v.y = (p0.y + p1.y) + (p2.y + p3.y) + bb.y + xv.y;
    v.z = (p0.z + p1.z) + (p2.z + p3.z) + bb.z + xv.z;
    v.w = (p0.w + p1.w) + (p2.w + p3.w) + bb.w + xv.w;
    float s = v.x + v.y + v.z + v.w;
    float q = v.x*v.x + v.y*v.y + v.z*v.z + v.w*v.w;
    #pragma unroll
    for (int o = 16; o; o >>= 1) {
        s += __shfl_xor_sync(0xffffffffu, s, o);
        q += __shfl_xor_sync(0xffffffffu, q, o);
    }
    if ((t & 31) == 0) { sS[t>>5] = s; sQ[t>>5] = q; }
    __syncthreads();
    s = sS[0] + sS[1] + sS[2] + sS[3];
    q = sQ[0] + sQ[1] + sQ[2] + sQ[3];
    float mu   = s * (1.0f/EE);
    float var  = q * (1.0f/EE) - mu*mu;
    float rstd = rsqrtf(var + 1e-5f);
    float4 lw = ((const float4*)w)[t];
    float4 lb = ((const float4*)b)[t];
    float4 th = ((const float4*)thf)[t];
    float4 x1;
    x1.x = (v.x - mu)*rstd*lw.x + lb.x;
    x1.y = (v.y - mu)*rstd*lw.y + lb.y;
    x1.z = (v.z - mu)*rstd*lw.z + lb.z;
    x1.w = (v.w - mu)*rstd*lw.w + lb.w;
    ((float4*)(g_x1 + row*EE))[t] = x1;
    float qx = __cosf(x1.x)*__cosf(th.x);
    float qy = __cosf(x1.y)*__cosf(th.y);
    float qz = __cosf(x1.z)*__cosf(th.z);
    float qw = __cosf(x1.w)*__cosf(th.w);
    *reinterpret_cast<uint2*>(g_qf_h + row*EE + t*4) =
        make_uint2(pack_h2(qx, qy), pack_h2(qz, qw));
}

__global__ void __launch_bounds__(128) ln2_kernel(
    const float* __restrict__ part, const float* __restrict__ bias,
    const float* __restrict__ res,
    const float* __restrict__ w,  const float* __restrict__ b,
    float* __restrict__ out)
{
    __shared__ float sS[4], sQ[4];
    const int row = blockIdx.x;
    const int t = threadIdx.x;
    float4 p0 = ((const float4*)(part + 0*BS*EE + row*EE))[t];
    float4 p1 = ((const float4*)(part + 1*BS*EE + row*EE))[t];
    float4 p2 = ((const float4*)(part + 2*BS*EE + row*EE))[t];
    float4 p3 = ((const float4*)(part + 3*BS*EE + row*EE))[t];
    float4 bb = ((const float4*)bias)[t];
    float4 rv = ((const float4*)(res + row*EE))[t];
    float4 v;
    v.x = (p0.x + p1.x) + (p2.x + p3.x) + bb.x + rv.x;
    v.y = (p0.y + p1.y) + (p2.y + p3.y) + bb.y + rv.y;
    v.z = (p0.z + p1.z) + (p2.z + p3.z) + bb.z + rv.z;
    v.w = (p0.w + p1.w) + (p2.w + p3.w) + bb.w + rv.w;
    float s = v.x + v.y + v.z + v.w;
    float q = v.x*v.x + v.y*v.y + v.z*v.z + v.w*v.w;
    #pragma unroll
    for (int o = 16; o; o >>= 1) {
        s += __shfl_xor_sync(0xffffffffu, s, o);
        q += __shfl_xor_sync(0xffffffffu, q, o);
    }
    if ((t & 31) == 0) { sS[t>>5] = s; sQ[t>>5] = q; }
    __syncthreads();
    s = sS[0] + sS[1] + sS[2] + sS[3];
    q = sQ[0] + sQ[1] + sQ[2] + sQ[3];
    float mu   = s * (1.0f/EE);
    float var  = q * (1.0f/EE) - mu*mu;
    float rstd = rsqrtf(var + 1e-5f);
    float4 lw = ((const float4*)w)[t];
    float4 lb = ((const float4*)b)[t];
    float4 o4;
    o4.x = (v.x - mu)*rstd*lw.x + lb.x;
    o4.y = (v.y - mu)*rstd*lw.y + lb.y;
    o4.z = (v.z - mu)*rstd*lw.z + lb.z;
    o4.w = (v.w - mu)*rstd*lw.w + lb.w;
    ((float4*)(out + row*EE))[t] = o4;
}

// =====================================================================
extern "C" void kernel_launch(void* const* d_in, const int* in_sizes, int n_in,
                              void* d_out, int out_size) {
    const float* x         = (const float*)d_in[0];
    const float* theta_at  = (const float*)d_in[1];
    const float* w_combine = (const float*)d_in[2];
    const float* b_combine = (const float*)d_in[3];
    const float* theta_ffn = (const float*)d_in[4];
    const float* w1        = (const float*)d_in[5];
    const float* b1        = (const float*)d_in[6];
    const float* w2        = (const float*)d_in[7];
    const float* b2        = (const float*)d_in[8];
    const float* ln1w      = (const float*)d_in[9];
    const float* ln1b      = (const float*)d_in[10];
    const float* ln2w      = (const float*)d_in[11];
    const float* ln2b      = (const float*)d_in[12];
    float* out = (float*)d_out;

    __half* d_attn_h; cudaGetSymbolAddress((void**)&d_attn_h, g_attn_h);
    float*  d_x1;     cudaGetSymbolAddress((void**)&d_x1,     g_x1);
    __half* d_qf_h;   cudaGetSymbolAddress((void**)&d_qf_h,   g_qf_h);
    __half* d_hdn_h;  cudaGetSymbolAddress((void**)&d_hdn_h,  g_hdn_h);
    float*  d_pre4;   cudaGetSymbolAddress((void**)&d_pre4,   g_pre4);
    __half2* d_wch;   cudaGetSymbolAddress((void**)&d_wch,    g_wch);
    __half2* d_w1h;   cudaGetSymbolAddress((void**)&d_w1h,    g_w1h);
    __half2* d_w2h;   cudaGetSymbolAddress((void**)&d_w2h,    g_w2h);

    const int WTOT = WC_E + W1_E + W2_E;
    wpack_kernel<<<(WTOT + 255)/256, 256>>>(w_combine, w1, w2);
    qkv_kernel<<<512, 256>>>(x, theta_at);
    attn_mma_kernel<<<1024, 256>>>();

    // combine: split-K x4 (K=128 each) -> g_pre4; ln1 reduces + bias + x
    mma_gemm_split_kernel<128><<<dim3(4, 64, 4), 256>>>(
        d_attn_h, d_wch, d_pre4, EE, EE);
    ln1_cos_kernel<<<BS, 128>>>(d_pre4, b_combine, x, ln1w, ln1b, theta_ffn);

    // ffn1: full-K, bias+relu -> g_hdn_h (grid already 1024)
    mma_gemm_ffn1_kernel<<<dim3(16, 64), 256>>>(d_qf_h, d_w1h, b1, d_hdn_h, FF);

    // ffn2: split-K x4 (K=512 each) -> g_pre4; ln2 reduces + b2 + x1
    mma_gemm_split_kernel<512><<<dim3(4, 64, 4), 256>>>(
        d_hdn_h, d_w2h, d_pre4, EE, FF);
    ln2_kernel<<<BS, 128>>>(d_pre4, b2, d_x1, ln2w, ln2b, out);
}

// round 16
// speedup vs baseline: 1.1692x; 1.0175x over previous
#include <cuda_runtime.h>
#include <cuda_fp16.h>
#include <math.h>
#include <stdint.h>

#define BB 2
#define SS 1024
#define EE 512
#define HH 64
#define DKK 8
#define FF 2048
#define BS (BB*SS)   // 2048

// ---- scratch (device globals: allocation-free) ----
__device__ float   g_q[BB*HH*SS*DKK];    // [B][H][S][8]
__device__ __half  g_attn_h[BS*EE];      // attention out (fp16)
__device__ float   g_x1[BS*EE];          // post-LN1 (f32, ffn2 residual)
__device__ __half  g_qf_h[BS*EE];        // cos(x1)*cos(theta) (fp16)
__device__ __half  g_hdn_h[BS*FF];       // FFN hidden (fp16)
__device__ float   g_pre4[4*BS*EE];      // split-K partials
// pre-packed fp16 weights, k-pair layout: Wh[kk][n] = (W[2kk][n], W[2kk+1][n])
__device__ __half2 g_wch[(EE/2)*EE];     // 256x512
__device__ __half2 g_w1h[(EE/2)*FF];     // 256x2048
__device__ __half2 g_w2h[(FF/2)*EE];     // 1024x512

__device__ __forceinline__ float ex2a(float x) {
    float r; asm("ex2.approx.f32 %0, %1;" : "=f"(r) : "f"(x)); return r;
}
__device__ __forceinline__ void mma_tf32u(float& c0, float& c1, float& c2, float& c3,
                                          uint32_t A0, uint32_t A1, uint32_t A2, uint32_t A3,
                                          uint32_t B0, uint32_t B1) {
    asm volatile(
        "mma.sync.aligned.m16n8k8.row.col.f32.tf32.tf32.f32 "
        "{%0,%1,%2,%3},{%4,%5,%6,%7},{%8,%9},{%0,%1,%2,%3};"
        : "+f"(c0), "+f"(c1), "+f"(c2), "+f"(c3)
        : "r"(A0), "r"(A1), "r"(A2), "r"(A3), "r"(B0), "r"(B1));
}
__device__ __forceinline__ void mma_f16(float* acc,
                                        uint32_t a0, uint32_t a1, uint32_t a2, uint32_t a3,
                                        uint32_t b0, uint32_t b1) {
    asm volatile(
        "mma.sync.aligned.m16n8k16.row.col.f32.f16.f16.f32 "
        "{%0,%1,%2,%3},{%4,%5,%6,%7},{%8,%9},{%0,%1,%2,%3};"
        : "+f"(acc[0]), "+f"(acc[1]), "+f"(acc[2]), "+f"(acc[3])
        : "r"(a0), "r"(a1), "r"(a2), "r"(a3), "r"(b0), "r"(b1));
}
__device__ __forceinline__ uint32_t pack_h2(float lo, float hi) {
    __half2 h = __floats2half2_rn(lo, hi);
    return *reinterpret_cast<uint32_t*>(&h);
}

// =====================================================================
// K0: merged prep — qkv (first 512 blocks) + weight pre-pack (rest)
// =====================================================================
#define WC_E ((EE/2)*EE)     // 131072
#define W1_E ((EE/2)*FF)     // 524288
#define W2_E ((FF/2)*EE)     // 524288
#define QKV_BLOCKS 512
#define WPACK_BLOCKS ((WC_E + W1_E + W2_E) / 256)   // 4608

__global__ void prep_kernel(const float* __restrict__ x,
                            const float* __restrict__ theta,
                            const float* __restrict__ wc,
                            const float* __restrict__ w1,
                            const float* __restrict__ w2) {
    if (blockIdx.x < QKV_BLOCKS) {
        int i = blockIdx.x * 256 + threadIdx.x;   // over B*S*H
        int h  = i & (HH-1);
        int bs = i >> 6;
        const float* xp = x + bs*EE + h*DKK;
        float4 xa = *(const float4*)xp;
        float4 xb = *(const float4*)(xp + 4);
        float c0 = __cosf(xa.x + theta[0]);
        float c1 = __cosf(xa.y + theta[1]);
        float c2 = __cosf(xa.z + theta[2]);
        float c3 = __cosf(xa.w + theta[3]);
        float c4 = __cosf(xb.x + theta[4]);
        float c5 = __cosf(xb.y + theta[5]);
        float c6 = __cosf(xb.z + theta[6]);
        float c7 = __cosf(xb.w + theta[7]);
        float o1 = c0*c1;
        float o2 = o1*c2;
        float o3 = o2*c3;
        float o4 = o3*c4;
        float o5 = o4*c5;
        float o6 = o5*c6;
        float o7 = o6*c7;
        float o0 = c1*c2*c3*c4*c5*c6*c7;
        int b = bs >> 10, s = bs & (SS-1);
        float* qp = g_q + (((b*HH + h)*SS) + s)*DKK;
        *(float4*)qp       = make_float4(o0, o1, o2, o3);
        *(float4*)(qp + 4) = make_float4(o4, o5, o6, o7);
    } else {
        int i = (blockIdx.x - QKV_BLOCKS) * 256 + threadIdx.x;
        if (i < WC_E) {
            int kk = i >> 9, n = i & 511;
            g_wch[i] = __floats2half2_rn(wc[(2*kk)*EE + n], wc[(2*kk+1)*EE + n]);
        } else if (i < WC_E + W1_E) {
            int j = i - WC_E;
            int kk = j >> 11, n = j & 2047;
            g_w1h[j] = __floats2half2_rn(w1[(2*kk)*FF + n], w1[(2*kk+1)*FF + n]);
        } else {
            int j = i - WC_E - W1_E;
            int kk = j >> 9, n = j & 511;
            g_w2h[j] = __floats2half2_rn(w2[(2*kk)*EE + n], w2[(2*kk+1)*EE + n]);
        }
    }
}

// =====================================================================
// K2: tensor-core attention (R10/R14 validated form, fp16 epilogue)
// =====================================================================
__global__ void __launch_bounds__(256, 4) attn_mma_kernel() {
    __shared__ float Ks[SS*12];
    const int bh   = blockIdx.x >> 3;
    const int tile = blockIdx.x & 7;

    const float* qsrc = g_q + bh*(SS*DKK);
    for (int j = threadIdx.x; j < SS*DKK/4; j += 256) {
        float4 v = ((const float4*)qsrc)[j];
        int t = j >> 1, hf = (j & 1) * 4;
        *(float4*)&Ks[t*12 + hf] = v;
    }
    __syncthreads();

    const int lane = threadIdx.x & 31, warp = threadIdx.x >> 5;
    const int g = lane >> 2, tc = lane & 3;
    const int sg = (g >> 1) + (g & 1)*4;
    const int row0 = tile*128 + warp*16;

    const float SCL = 0.35355339059f * 1.44269504089f;
    const uint32_t qa0 = __float_as_uint(Ks[(row0+g  )*12 + tc  ] * SCL);
    const uint32_t qa1 = __float_as_uint(Ks[(row0+g+8)*12 + tc  ] * SCL);
    const uint32_t qa2 = __float_as_uint(Ks[(row0+g  )*12 + tc+4] * SCL);
    const uint32_t qa3 = __float_as_uint(Ks[(row0+g+8)*12 + tc+4] * SCL);

    float oa0=0.f, oa1=0.f, oa2=0.f, oa3=0.f;
    float ob0=0.f, ob1=0.f, ob2=0.f, ob3=0.f;
    float ra0=0.f, ra1=0.f, rb0=0.f, rb1=0.f;

    #pragma unroll 2
    for (int t0 = 0; t0 < SS; t0 += 16) {
        const int tA = t0, tB = t0 + 8;
        uint32_t sA0 = __float_as_uint(Ks[(tA+sg)*12 + tc  ]);
        uint32_t sA1 = __float_as_uint(Ks[(tA+sg)*12 + tc+4]);
        uint32_t sB0 = __float_as_uint(Ks[(tB+sg)*12 + tc  ]);
        uint32_t sB1 = __float_as_uint(Ks[(tB+sg)*12 + tc+4]);
        float a0=0.f,a1=0.f,a2=0.f,a3=0.f;
        float b0=0.f,b1=0.f,b2=0.f,b3=0.f;
        mma_tf32u(a0,a1,a2,a3, qa0,qa1,qa2,qa3, sA0,sA1);
        mma_tf32u(b0,b1,b2,b3, qa0,qa1,qa2,qa3, sB0,sB1);

        float pA0 = ex2a(a0), pA1 = ex2a(a1), pA2 = ex2a(a2), pA3 = ex2a(a3);
        float pB0 = ex2a(b0), pB1 = ex2a(b1), pB2 = ex2a(b2), pB3 = ex2a(b3);
        ra0 += pA0 + pA1;  ra1 += pA2 + pA3;
        rb0 += pB0 + pB1;  rb1 += pB2 + pB3;

        uint32_t vA0 = __float_as_uint(Ks[(tA+tc  )*12 + g]);
        uint32_t vA1 = __float_as_uint(Ks[(tA+tc+4)*12 + g]);
        uint32_t vB0 = __float_as_uint(Ks[(tB+tc  )*12 + g]);
        uint32_t vB1 = __float_as_uint(Ks[(tB+tc+4)*12 + g]);
        mma_tf32u(oa0,oa1,oa2,oa3,
                  __float_as_uint(pA0), __float_as_uint(pA2),
                  __float_as_uint(pA1), __float_as_uint(pA3), vA0, vA1);
        mma_tf32u(ob0,ob1,ob2,ob3,
                  __float_as_uint(pB0), __float_as_uint(pB2),
                  __float_as_uint(pB1), __float_as_uint(pB3), vB0, vB1);
    }

    float rs0 = ra0 + rb0, rs1 = ra1 + rb1;
    rs0 += __shfl_xor_sync(0xffffffffu, rs0, 1);
    rs0 += __shfl_xor_sync(0xffffffffu, rs0, 2);
    rs1 += __shfl_xor_sync(0xffffffffu, rs1, 1);
    rs1 += __shfl_xor_sync(0xffffffffu, rs1, 2);
    float i0 = 1.0f / rs0, i1 = 1.0f / rs1;

    const int b = bh >> 6, h = bh & (HH-1);
    const int r0 = row0 + g, r1 = r0 + 8;
    *reinterpret_cast<uint32_t*>(g_attn_h + (b*SS + r0)*EE + h*DKK + 2*tc)
        = pack_h2((oa0+ob0)*i0, (oa1+ob1)*i0);
    *reinterpret_cast<uint32_t*>(g_attn_h + (b*SS + r1)*EE + h*DKK + 2*tc)
        = pack_h2((oa2+ob2)*i1, (oa3+ob3)*i1);
}

// =====================================================================
// combine split-K GEMM, KCH=128 (4 chunks): ALL chunks staged upfront.
// One LDG wave (MLP=20) fully hides gmem latency; then pure compute.
// =====================================================================
__global__ void __launch_bounds__(256, 2) mma_gemm_split128_kernel(
    const __half* __restrict__ A, const __half2* __restrict__ Wh,
    float* __restrict__ partial, int N, int KTOT)
{
    __shared__ __half As[32][40];
    __shared__ __half2 Bs[16][136];

    const int rowbase = blockIdx.y * 32;
    const int colbase = blockIdx.x * 128;
    const int ks      = blockIdx.z;
    const int tid  = threadIdx.x;
    const int warp = tid >> 5, lane = tid & 31;
    const int wm = warp >> 2;
    const int wn = warp & 3;
    const int g  = lane >> 2, tc = lane & 3;

    const __half2* Wp = Wh + (ks * 64) * N;     // KCH/2 = 64 k-pairs
    float* outp = partial + ks * (BS * N);

    float acc[4][4];
    #pragma unroll
    for (int i = 0; i < 4; i++)
        #pragma unroll
        for (int j = 0; j < 4; j++) acc[i][j] = 0.f;

    const int arow = tid >> 3, ak = (tid & 7) * 4;
    const __half* Aptr = A + (rowbase + arow) * KTOT + ks * 128 + ak;
    const int blin_kk = tid >> 6;               // base k-pair for item i=0
    const int blin_u2 = (tid & 63) * 2;

    // stage everything upfront: 4 A + 16 B LDG.64 in flight
    uint2 aReg[4], bReg[16];
    #pragma unroll
    for (int c = 0; c < 4; c++)
        aReg[c] = *(const uint2*)(Aptr + c*32);
    #pragma unroll
    for (int c = 0; c < 4; c++)
        #pragma unroll
        for (int i = 0; i < 4; i++) {
            int kk = c*16 + blin_kk + i*4;
            bReg[c*4 + i] = *(const uint2*)(Wp + kk * N + colbase + blin_u2);
        }

    #pragma unroll
    for (int ch = 0; ch < 4; ch++) {
        __syncthreads();
        *reinterpret_cast<uint2*>(&As[arow][ak]) = aReg[ch];
        #pragma unroll
        for (int i = 0; i < 4; i++) {
            int kk = blin_kk + i*4;
            *reinterpret_cast<uint2*>(&Bs[kk][blin_u2]) = bReg[ch*4 + i];
        }
        __syncthreads();

        #pragma unroll
        for (int s = 0; s < 2; s++) {
            const int kc = s*16 + 2*tc;
            uint32_t a0 = *reinterpret_cast<const uint32_t*>(&As[wm*16 + g    ][kc    ]);
            uint32_t a1 = *reinterpret_cast<const uint32_t*>(&As[wm*16 + g + 8][kc    ]);
            uint32_t a2 = *reinterpret_cast<const uint32_t*>(&As[wm*16 + g    ][kc + 8]);
            uint32_t a3 = *reinterpret_cast<const uint32_t*>(&As[wm*16 + g + 8][kc + 8]);
            #pragma unroll
            for (int nt = 0; nt < 4; nt++) {
                int col = wn*32 + nt*8 + g;
                uint32_t b0 = *reinterpret_cast<const uint32_t*>(&Bs[s*8 + tc    ][col]);
                uint32_t b1 = *reinterpret_cast<const uint32_t*>(&Bs[s*8 + tc + 4][col]);
                mma_f16(acc[nt], a0, a1, a2, a3, b0, b1);
            }
        }
    }

    #pragma unroll
    for (int nt = 0; nt < 4; nt++) {
        int col = colbase + wn*32 + nt*8 + 2*tc;
        int r0 = rowbase + wm*16 + g;
        int r1 = r0 + 8;
        *(float2*)(outp + r0*N + col) = make_float2(acc[nt][0], acc[nt][1]);
        *(float2*)(outp + r1*N + col) = make_float2(acc[nt][2], acc[nt][3]);
    }
}

// =====================================================================
// K=512 GEMM body with DEPTH-2 register prefetch (ping-pong, unroll 2).
// PARTIAL: raw f32 split output; else bias(+relu) fp16 output.
// =====================================================================
template<bool PARTIAL, bool RELU>
__global__ void __launch_bounds__(256, 3) mma_gemm_k512_kernel(
    const __half* __restrict__ A, const __half2* __restrict__ Wh,
    const float* __restrict__ bias,
    float* __restrict__ partial, __half* __restrict__ outh, int N, int KTOT)
{
    __shared__ __half As[32][40];
    __shared__ __half2 Bs[16][136];

    const int rowbase = blockIdx.y * 32;
    const int colbase = blockIdx.x * 128;
    const int ks      = blockIdx.z;
    const int tid  = threadIdx.x;
    const int warp = tid >> 5, lane = tid & 31;
    const int wm = warp >> 2;
    const int wn = warp & 3;
    const int g  = lane >> 2, tc = lane & 3;

    const __half2* Wp = Wh + (ks * 256) * N;    // KCH=512 -> 256 k-pairs
    float* outp = PARTIAL ? (partial + ks * (BS * N)) : nullptr;

    float acc[4][4];
    #pragma unroll
    for (int i = 0; i < 4; i++)
        #pragma unroll
        for (int j = 0; j < 4; j++) acc[i][j] = 0.f;

    const int arow = tid >> 3, ak = (tid & 7) * 4;
    const __half* Aptr = A + (rowbase + arow) * KTOT + ks * 512 + ak;
    const int blin_kk = tid >> 6;
    const int blin_u2 = (tid & 63) * 2;

    const int NCHUNK = 16;
    uint2 aR[2]; uint2 bR[2][4];
    #pragma unroll
    for (int p = 0; p < 2; p++) {
        aR[p] = *(const uint2*)(Aptr + p*32);
        #pragma unroll
        for (int i = 0; i < 4; i++) {
            int kk = p*16 + blin_kk + i*4;
            bR[p][i] = *(const uint2*)(Wp + kk * N + colbase + blin_u2);
        }
    }

    #pragma unroll 2
    for (int ch = 0; ch < NCHUNK; ch++) {
        const int s2 = ch & 1;
        __syncthreads();
        *reinterpret_cast<uint2*>(&As[arow][ak]) = aR[s2];
        #pragma unroll
        for (int i = 0; i < 4; i++) {
            int kk = blin_kk + i*4;
            *reinterpret_cast<uint2*>(&Bs[kk][blin_u2]) = bR[s2][i];
        }
        __syncthreads();

        if (ch + 2 < NCHUNK) {
            aR[s2] = *(const uint2*)(Aptr + (ch+2)*32);
            #pragma unroll
            for (int i = 0; i < 4; i++) {
                int kk = (ch+2)*16 + blin_kk + i*4;
                bR[s2][i] = *(const uint2*)(Wp + kk * N + colbase + blin_u2);
            }
        }

        #pragma unroll
        for (int s = 0; s < 2; s++) {
            const int kc = s*16 + 2*tc;
            uint32_t a0 = *reinterpret_cast<const uint32_t*>(&As[wm*16 + g    ][kc    ]);
            uint32_t a1 = *reinterpret_cast<const uint32_t*>(&As[wm*16 + g + 8][kc    ]);
            uint32_t a2 = *reinterpret_cast<const uint32_t*>(&As[wm*16 + g    ][kc + 8]);
            uint32_t a3 = *reinterpret_cast<const uint32_t*>(&As[wm*16 + g + 8][kc + 8]);
            #pragma unroll
            for (int nt = 0; nt < 4; nt++) {
                int col = wn*32 + nt*8 + g;
                uint32_t b0 = *reinterpret_cast<const uint32_t*>(&Bs[s*8 + tc    ][col]);
                uint32_t b1 = *reinterpret_cast<const uint32_t*>(&Bs[s*8 + tc + 4][col]);
                mma_f16(acc[nt], a0, a1, a2, a3, b0, b1);
            }
        }
    }

    #pragma unroll
    for (int nt = 0; nt < 4; nt++) {
        int col = colbase + wn*32 + nt*8 + 2*tc;
        int r0 = rowbase + wm*16 + g;
        int r1 = r0 + 8;
        if (PARTIAL) {
            *(float2*)(outp + r0*N + col) = make_float2(acc[nt][0], acc[nt][1]);
            *(float2*)(outp + r1*N + col) = make_float2(acc[nt][2], acc[nt][3]);
        } else {
            float bx = bias[col], by = bias[col+1];
            float v00 = acc[nt][0] + bx, v01 = acc[nt][1] + by;
            float v10 = acc[nt][2] + bx, v11 = acc[nt][3] + by;
            if (RELU) {
                v00 = fmaxf(v00, 0.f); v01 = fmaxf(v01, 0.f);
                v10 = fmaxf(v10, 0.f); v11 = fmaxf(v11, 0.f);
            }
            *reinterpret_cast<uint32_t*>(outh + r0*N + col) = pack_h2(v00, v01);
            *reinterpret_cast<uint32_t*>(outh + r1*N + col) = pack_h2(v10, v11);
        }
    }
}

// =====================================================================
// LN kernels: sum 4 split-K partials + bias + residual, then LN
// =====================================================================
__global__ void __launch_bounds__(128) ln1_cos_kernel(
    const float* __restrict__ part, const float* __restrict__ bias,
    const float* __restrict__ x,
    const float* __restrict__ w,  const float* __restrict__ b,
    const float* __restrict__ thf)
{
    __shared__ float sS[4], sQ[4];
    const int row = blockIdx.x;
    const int t = threadIdx.x;
    float4 p0 = ((const float4*)(part + 0*BS*EE + row*EE))[t];
    float4 p1 = ((const float4*)(part + 1*BS*EE + row*EE))[t];
    float4 p2 = ((const float4*)(part + 2*BS*EE + row*EE))[t];
    float4 p3 = ((const float4*)(part + 3*BS*EE + row*EE))[t];
    float4 bb = ((const float4*)bias)[t];
    float4 xv = ((const float4*)(x + row*EE))[t];
    float4 v;
    v.x = (p0.x + p1.x) + (p2.x + p3.x) + bb.x + xv.x;
    v.y = (p0.y + p1.y) + (p2.y + p3.y) + bb.y + xv.y;
    v.z = (p0.z + p1.z) + (p2.z + p3.z) + bb.z + xv.z;
    v.w = (p0.w + p1.w) + (p2.w + p3.w) + bb.w + xv.w;
    float s = v.x + v.y + v.z + v.w;
    float q = v.x*v.x + v.y*v.y + v.z*v.z + v.w*v.w;
    #pragma unroll
    for (int o = 16; o; o >>= 1) {
        s += __shfl_xor_sync(0xffffffffu, s, o);
        q += __shfl_xor_sync(0xffffffffu, q, o);
    }
    if ((t & 31) == 0) { sS[t>>5] = s; sQ[t>>5] = q; }
    __syncthreads();
    s = sS[0] + sS[1] + sS[2] + sS[3];
    q = sQ[0] + sQ[1] + sQ[2] + sQ[3];
    float mu   = s * (1.0f/EE);
    float var  = q * (1.0f/EE) - mu*mu;
    float rstd = rsqrtf(var + 1e-5f);
    float4 lw = ((const float4*)w)[t];
    float4 lb = ((const float4*)b)[t];
    float4 th = ((const float4*)thf)[t];
    float4 x1;
    x1.x = (v.x - mu)*rstd*lw.x + lb.x;
    x1.y = (v.y - mu)*rstd*lw.y + lb.y;
    x1.z = (v.z - mu)*rstd*lw.z + lb.z;
    x1.w = (v.w - mu)*rstd*lw.w + lb.w;
    ((float4*)(g_x1 + row*EE))[t] = x1;
    float qx = __cosf(x1.x)*__cosf(th.x);
    float qy = __cosf(x1.y)*__cosf(th.y);
    float qz = __cosf(x1.z)*__cosf(th.z);
    float qw = __cosf(x1.w)*__cosf(th.w);
    *reinterpret_cast<uint2*>(g_qf_h + row*EE + t*4) =
        make_uint2(pack_h2(qx, qy), pack_h2(qz, qw));
}

__global__ void __launch_bounds__(128) ln2_kernel(
    const float* __restrict__ part, const float* __restrict__ bias,
    const float* __restrict__ res,
    const float* __restrict__ w,  const float* __restrict__ b,
    float* __restrict__ out)
{
    __shared__ float sS[4], sQ[4];
    const int row = blockIdx.x;
    const int t = threadIdx.x;
    float4 p0 = ((const float4*)(part + 0*BS*EE + row*EE))[t];
    float4 p1 = ((const float4*)(part + 1*BS*EE + row*EE))[t];
    float4 p2 = ((const float4*)(part + 2*BS*EE + row*EE))[t];
    float4 p3 = ((const float4*)(part + 3*BS*EE + row*EE))[t];
    float4 bb = ((const float4*)bias)[t];
    float4 rv = ((const float4*)(res + row*EE))[t];
    float4 v;
    v.x = (p0.x + p1.x) + (p2.x + p3.x) + bb.x + rv.x;
    v.y = (p0.y + p1.y) + (p2.y + p3.y) + bb.y + rv.y;
    v.z = (p0.z + p1.z) + (p2.z + p3.z) + bb.z + rv.z;
    v.w = (p0.w + p1.w) + (p2.w + p3.w) + bb.w + rv.w;
    float s = v.x + v.y + v.z + v.w;
    float q = v.x*v.x + v.y*v.y + v.z*v.z + v.w*v.w;
    #pragma unroll
    for (int o = 16; o; o >>= 1) {
        s += __shfl_xor_sync(0xffffffffu, s, o);
        q += __shfl_xor_sync(0xffffffffu, q, o);
    }
    if ((t & 31) == 0) { sS[t>>5] = s; sQ[t>>5] = q; }
    __syncthreads();
    s = sS[0] + sS[1] + sS[2] + sS[3];
    q = sQ[0] + sQ[1] + sQ[2] + sQ[3];
    float mu   = s * (1.0f/EE);
    float var  = q * (1.0f/EE) - mu*mu;
    float rstd = rsqrtf(var + 1e-5f);
    float4 lw = ((const float4*)w)[t];
    float4 lb = ((const float4*)b)[t];
    float4 o4;
    o4.x = (v.x - mu)*rstd*lw.x + lb.x;
    o4.y = (v.y - mu)*rstd*lw.y + lb.y;
    o4.z = (v.z - mu)*rstd*lw.z + lb.z;
    o4.w = (v.w - mu)*rstd*lw.w + lb.w;
    ((float4*)(out + row*EE))[t] = o4;
}

// =====================================================================
extern "C" void kernel_launch(void* const* d_in, const int* in_sizes, int n_in,
                              void* d_out, int out_size) {
    const float* x         = (const float*)d_in[0];
    const float* theta_at  = (const float*)d_in[1];
    const float* w_combine = (const float*)d_in[2];
    const float* b_combine = (const float*)d_in[3];
    const float* theta_ffn = (const float*)d_in[4];
    const float* w1        = (const float*)d_in[5];
    const float* b1        = (const float*)d_in[6];
    const float* w2        = (const float*)d_in[7];
    const float* b2        = (const float*)d_in[8];
    const float* ln1w      = (const float*)d_in[9];
    const float* ln1b      = (const float*)d_in[10];
    const float* ln2w      = (const float*)d_in[11];
    const float* ln2b      = (const float*)d_in[12];
    float* out = (float*)d_out;

    __half* d_attn_h; cudaGetSymbolAddress((void**)&d_attn_h, g_attn_h);
    float*  d_x1;     cudaGetSymbolAddress((void**)&d_x1,     g_x1);
    __half* d_qf_h;   cudaGetSymbolAddress((void**)&d_qf_h,   g_qf_h);
    __half* d_hdn_h;  cudaGetSymbolAddress((void**)&d_hdn_h,  g_hdn_h);
    float*  d_pre4;   cudaGetSymbolAddress((void**)&d_pre4,   g_pre4);
    __half2* d_wch;   cudaGetSymbolAddress((void**)&d_wch,    g_wch);
    __half2* d_w1h;   cudaGetSymbolAddress((void**)&d_w1h,    g_w1h);
    __half2* d_w2h;   cudaGetSymbolAddress((void**)&d_w2h,    g_w2h);

    prep_kernel<<<QKV_BLOCKS + WPACK_BLOCKS, 256>>>(x, theta_at,
                                                    w_combine, w1, w2);
    attn_mma_kernel<<<1024, 256>>>();

    // combine: split-K x4 (KCH=128, all-upfront staging) -> g_pre4
    mma_gemm_split128_kernel<<<dim3(4, 64, 4), 256>>>(
        d_attn_h, d_wch, d_pre4, EE, EE);
    ln1_cos_kernel<<<BS, 128>>>(d_pre4, b_combine, x, ln1w, ln1b, theta_ffn);

    // ffn1: K=512 full, depth-2 prefetch, bias+relu -> fp16
    mma_gemm_k512_kernel<false, true><<<dim3(16, 64, 1), 256>>>(
        d_qf_h, d_w1h, b1, nullptr, d_hdn_h, FF, EE);

    // ffn2: split-K x4 (KCH=512, depth-2 prefetch) -> g_pre4
    mma_gemm_k512_kernel<true, false><<<dim3(4, 64, 4), 256>>>(
        d_hdn_h, d_w2h, nullptr, d_pre4, nullptr, EE, FF);
    ln2_kernel<<<BS, 128>>>(d_pre4, b2, d_x1, ln2w, ln2b, out);
}